// round 1
// baseline (speedup 1.0000x reference)
#include <cuda_runtime.h>
#include <cuda_bf16.h>
#include <cstdint>

// Shapes (fixed by problem)
#define B   32
#define N   2048
#define VD  256
#define LR  64
#define EMB 256
#define ROWS (B*N)          // 65536
#define EPS_DIAG 1e-6f
#define EPS_BN   1e-5f

// Scratch (device globals; no allocation allowed)
__device__ float g_W[128 * 256];      // interleaved: row c even -> W1[c/2], odd -> W2[c/2]
__device__ float g_bias[128];
__device__ float g_right[(size_t)ROWS * LR];   // 16 MB
__device__ float g_dr[ROWS];
__device__ float g_s[B * LR];
__device__ float g_vfinal[B * VD];

// ---------------------------------------------------------------------------
// Kernel A: weight norm + zero accumulators
// grid 128, block 256
__global__ void k_weightnorm(const float* __restrict__ U1_v, const float* __restrict__ U1_g,
                             const float* __restrict__ U1_b, const float* __restrict__ U2_v,
                             const float* __restrict__ U2_g, const float* __restrict__ U2_b)
{
    int row = blockIdx.x;          // 0..127 interleaved
    int l = row >> 1;
    bool odd = row & 1;
    const float* v = (odd ? U2_v : U1_v) + l * VD;
    const float* g = odd ? U2_g : U1_g;
    const float* bb = odd ? U2_b : U1_b;
    int tid = threadIdx.x;

    float x = v[tid];
    float ss = x * x;
    // block reduce (8 warps)
    #pragma unroll
    for (int off = 16; off >= 1; off >>= 1) ss += __shfl_xor_sync(0xffffffff, ss, off);
    __shared__ float warp_ss[8];
    __shared__ float scale_sh;
    if ((tid & 31) == 0) warp_ss[tid >> 5] = ss;
    __syncthreads();
    if (tid == 0) {
        float tot = 0.f;
        #pragma unroll
        for (int w = 0; w < 8; w++) tot += warp_ss[w];
        scale_sh = g[l] * rsqrtf(tot);
    }
    __syncthreads();
    g_W[row * 256 + tid] = x * scale_sh;
    if (tid == 0) g_bias[row] = bb[l];

    // zero s and vfinal
    int idx = blockIdx.x * 256 + tid;
    if (idx < B * LR) g_s[idx] = 0.f;
    if (idx < B * VD) g_vfinal[idx] = 0.f;
}

// ---------------------------------------------------------------------------
// Kernel C: fused GEMM [65536 x 256] @ W^T[256 x 128] + relu + dr + s + right
// grid 512 (row tiles of 128), block 256, each thread 8x8 micro-tile.
__global__ void __launch_bounds__(256, 2) k_main(const float* __restrict__ Vmat)
{
    __shared__ float As[32][132];   // As[k][row]
    __shared__ float Bs[32][132];   // Bs[k][col]
    __shared__ float s_blk[64];

    int tid = threadIdx.x;
    int tileRow0 = blockIdx.x * 128;
    int batch = blockIdx.x >> 4;    // 2048/128 = 16 tiles per batch

    if (tid < 64) s_blk[tid] = 0.f;

    int ty = tid >> 4, tx = tid & 15;
    int row_base = ty * 8, col_base = tx * 8;

    float acc[8][8];
    #pragma unroll
    for (int i = 0; i < 8; i++)
        #pragma unroll
        for (int j = 0; j < 8; j++) acc[i][j] = 0.f;

    const float* Vbase = Vmat + (size_t)tileRow0 * VD;

    for (int kt = 0; kt < 8; kt++) {
        int k0 = kt * 32;
        __syncthreads();
        #pragma unroll
        for (int i = 0; i < 16; i++) {
            int idx = tid + i * 256;
            int r = idx >> 5, k = idx & 31;
            As[k][r] = Vbase[(size_t)r * VD + k0 + k];
        }
        #pragma unroll
        for (int i = 0; i < 16; i++) {
            int idx = tid + i * 256;
            int c = idx >> 5, k = idx & 31;
            Bs[k][c] = g_W[c * 256 + k0 + k];
        }
        __syncthreads();
        #pragma unroll
        for (int k = 0; k < 32; k++) {
            float4 a0 = *(const float4*)&As[k][row_base];
            float4 a1 = *(const float4*)&As[k][row_base + 4];
            float4 b0 = *(const float4*)&Bs[k][col_base];
            float4 b1 = *(const float4*)&Bs[k][col_base + 4];
            float a[8] = {a0.x, a0.y, a0.z, a0.w, a1.x, a1.y, a1.z, a1.w};
            float b[8] = {b0.x, b0.y, b0.z, b0.w, b1.x, b1.y, b1.z, b1.w};
            #pragma unroll
            for (int i = 0; i < 8; i++)
                #pragma unroll
                for (int j = 0; j < 8; j++) acc[i][j] = fmaf(a[i], b[j], acc[i][j]);
        }
    }

    // Epilogue: bias + relu, per-row d & dr (pairs = adjacent cols), store right, accumulate s
    float bias_r[8];
    #pragma unroll
    for (int j = 0; j < 8; j++) bias_r[j] = g_bias[col_base + j];

    float s_local[4] = {0.f, 0.f, 0.f, 0.f};

    #pragma unroll
    for (int i = 0; i < 8; i++) {
        float Rv[4], Lv[4];
        float d = 0.f;
        #pragma unroll
        for (int p = 0; p < 4; p++) {
            float r = fmaxf(acc[i][2 * p]     + bias_r[2 * p],     0.f);
            float l = fmaxf(acc[i][2 * p + 1] + bias_r[2 * p + 1], 0.f);
            Rv[p] = r; Lv[p] = l;
            d = fmaf(l, r, d);
        }
        // reduce over the 16 tx-lanes (offsets 8..1 stay inside each 16-lane half)
        #pragma unroll
        for (int off = 8; off >= 1; off >>= 1) d += __shfl_xor_sync(0xffffffff, d, off);
        float dr = rsqrtf(d + EPS_DIAG);
        int row = tileRow0 + row_base + i;
        if (tx == 0) g_dr[row] = dr;
        float4 rq = make_float4(Rv[0], Rv[1], Rv[2], Rv[3]);
        *(float4*)(g_right + (size_t)row * LR + tx * 4) = rq;
        #pragma unroll
        for (int p = 0; p < 4; p++) s_local[p] = fmaf(dr, Lv[p], s_local[p]);
    }

    // accumulate s into block smem, then global
    #pragma unroll
    for (int p = 0; p < 4; p++) atomicAdd(&s_blk[tx * 4 + p], s_local[p]);
    __syncthreads();
    if (tid < 64) atomicAdd(&g_s[batch * LR + tid], s_blk[tid]);
}

// ---------------------------------------------------------------------------
// Kernel D: c[m] = N+1 - dr[m]*(s . right[m]); v_final += (1/N) * c[m] * Vmat[m,:]
// grid (8 chunks, 32 batches), block 256 (thread = one m for phase 1, one d for phase 2)
__global__ void __launch_bounds__(256) k_final(const float* __restrict__ Vmat)
{
    __shared__ float s_sh[64];
    __shared__ float c_sh[256];
    int tid = threadIdx.x;
    int b = blockIdx.y;
    int m0 = blockIdx.x * 256;

    if (tid < 64) s_sh[tid] = g_s[b * LR + tid];
    __syncthreads();

    int row = b * N + m0 + tid;
    const float4* rp = (const float4*)(g_right + (size_t)row * LR);
    float dot = 0.f;
    #pragma unroll
    for (int q = 0; q < 16; q++) {
        float4 v = rp[q];
        dot = fmaf(v.x, s_sh[q * 4 + 0], dot);
        dot = fmaf(v.y, s_sh[q * 4 + 1], dot);
        dot = fmaf(v.z, s_sh[q * 4 + 2], dot);
        dot = fmaf(v.w, s_sh[q * 4 + 3], dot);
    }
    c_sh[tid] = (float)(N + 1) - g_dr[row] * dot;
    __syncthreads();

    const float* Vp = Vmat + ((size_t)b * N + m0) * VD + tid;
    float vacc = 0.f;
    #pragma unroll 8
    for (int m = 0; m < 256; m++) vacc = fmaf(c_sh[m], Vp[(size_t)m * VD], vacc);
    atomicAdd(&g_vfinal[b * VD + tid], vacc * (1.0f / (float)N));
}

// ---------------------------------------------------------------------------
// Kernel E: feat = v_final @ W_lin^T + b_lin; BatchNorm over B (biased var)
// grid 256 (one per embed col e), block 1024 (warp w = batch b)
__global__ void __launch_bounds__(1024) k_bn(const float* __restrict__ W_lin,
                                             const float* __restrict__ b_lin,
                                             const float* __restrict__ gamma,
                                             const float* __restrict__ beta,
                                             float* __restrict__ out)
{
    int e = blockIdx.x;
    int tid = threadIdx.x;
    int w = tid >> 5, lane = tid & 31;

    const float* wrow = W_lin + e * VD;
    const float* vrow = g_vfinal + w * VD;
    float part = 0.f;
    #pragma unroll
    for (int q = 0; q < 8; q++) {
        int d0 = lane + q * 32;
        part = fmaf(vrow[d0], wrow[d0], part);
    }
    #pragma unroll
    for (int off = 16; off >= 1; off >>= 1) part += __shfl_xor_sync(0xffffffff, part, off);

    __shared__ float feats[32];
    __shared__ float stats[2];
    if (lane == 0) feats[w] = part + b_lin[e];
    __syncthreads();

    if (tid < 32) {
        float f = feats[tid];
        float mu = f;
        #pragma unroll
        for (int off = 16; off >= 1; off >>= 1) mu += __shfl_xor_sync(0xffffffff, mu, off);
        mu *= (1.0f / 32.0f);
        float df = f - mu;
        float vv = df * df;
        #pragma unroll
        for (int off = 16; off >= 1; off >>= 1) vv += __shfl_xor_sync(0xffffffff, vv, off);
        vv *= (1.0f / 32.0f);
        if (tid == 0) { stats[0] = mu; stats[1] = vv; }
    }
    __syncthreads();
    if (lane == 0) {
        float mu = stats[0], var = stats[1];
        out[w * EMB + e] = (feats[w] - mu) * rsqrtf(var + EPS_BN) * gamma[e] + beta[e];
    }
}

// ---------------------------------------------------------------------------
extern "C" void kernel_launch(void* const* d_in, const int* in_sizes, int n_in,
                              void* d_out, int out_size)
{
    const float* Vmat  = (const float*)d_in[0];
    const float* U1_v  = (const float*)d_in[1];
    const float* U1_g  = (const float*)d_in[2];
    const float* U1_b  = (const float*)d_in[3];
    const float* U2_v  = (const float*)d_in[4];
    const float* U2_g  = (const float*)d_in[5];
    const float* U2_b  = (const float*)d_in[6];
    const float* W_lin = (const float*)d_in[7];
    const float* b_lin = (const float*)d_in[8];
    const float* gamma = (const float*)d_in[9];
    const float* beta  = (const float*)d_in[10];
    float* out = (float*)d_out;

    k_weightnorm<<<128, 256>>>(U1_v, U1_g, U1_b, U2_v, U2_g, U2_b);
    k_main<<<ROWS / 128, 256>>>(Vmat);
    k_final<<<dim3(8, B), 256>>>(Vmat);
    k_bn<<<EMB, 1024>>>(W_lin, b_lin, gamma, beta, out);
}

// round 3
// speedup vs baseline: 2.0186x; 2.0186x over previous
#include <cuda_runtime.h>
#include <cuda_bf16.h>
#include <cstdint>

#define B   32
#define N   2048
#define VD  256
#define LR  64
#define EMB 256
#define ROWS (B*N)
#define EPS_DIAG 1e-6f
#define EPS_BN   1e-5f

// Scratch (device globals)
__device__ float g_W[128 * 256];      // interleaved: row c even -> W1[c/2], odd -> W2[c/2]
__device__ float g_bias[128];
__device__ float g_right[(size_t)ROWS * LR];   // 16 MB
__device__ float g_dr[ROWS];
__device__ float g_s[B * LR];
__device__ float g_vfinal[B * VD];

__device__ __forceinline__ uint32_t to_tf32(float x) {
    uint32_t y;
    asm("cvt.rna.tf32.f32 %0, %1;" : "=r"(y) : "f"(x));
    return y;
}

__device__ __forceinline__ void mma_tf32(float c[4], const uint32_t a[4], const uint32_t b[2]) {
    asm volatile(
        "mma.sync.aligned.m16n8k8.row.col.f32.tf32.tf32.f32 "
        "{%0,%1,%2,%3}, {%4,%5,%6,%7}, {%8,%9}, {%0,%1,%2,%3};"
        : "+f"(c[0]), "+f"(c[1]), "+f"(c[2]), "+f"(c[3])
        : "r"(a[0]), "r"(a[1]), "r"(a[2]), "r"(a[3]), "r"(b[0]), "r"(b[1]));
}

// ---------------------------------------------------------------------------
// Kernel A: weight norm + zero accumulators.  grid 128, block 256
__global__ void k_weightnorm(const float* __restrict__ U1_v, const float* __restrict__ U1_g,
                             const float* __restrict__ U1_b, const float* __restrict__ U2_v,
                             const float* __restrict__ U2_g, const float* __restrict__ U2_b)
{
    int row = blockIdx.x;
    int l = row >> 1;
    bool odd = row & 1;
    const float* v = (odd ? U2_v : U1_v) + l * VD;
    const float* g = odd ? U2_g : U1_g;
    const float* bb = odd ? U2_b : U1_b;
    int tid = threadIdx.x;

    float x = v[tid];
    float ss = x * x;
    #pragma unroll
    for (int off = 16; off >= 1; off >>= 1) ss += __shfl_xor_sync(0xffffffff, ss, off);
    __shared__ float warp_ss[8];
    __shared__ float scale_sh;
    if ((tid & 31) == 0) warp_ss[tid >> 5] = ss;
    __syncthreads();
    if (tid == 0) {
        float tot = 0.f;
        #pragma unroll
        for (int w = 0; w < 8; w++) tot += warp_ss[w];
        scale_sh = g[l] * rsqrtf(tot);
    }
    __syncthreads();
    g_W[row * 256 + tid] = x * scale_sh;
    if (tid == 0) g_bias[row] = bb[l];

    int idx = blockIdx.x * 256 + tid;
    if (idx < B * LR) g_s[idx] = 0.f;
    if (idx < B * VD) g_vfinal[idx] = 0.f;
}

// ---------------------------------------------------------------------------
// Kernel C: tf32 tensor-core GEMM [65536x256] @ W^T[256x128] + fused epilogue.
// grid 512 (row tiles of 128), block 256 (8 warps: 4 m x 2 n).
__global__ void __launch_bounds__(256, 2) k_main(const float* __restrict__ Vmat)
{
    __shared__ uint32_t As[128][36];   // [row][k-in-chunk] (tf32 bits), pad 36
    __shared__ uint32_t Bs[128][36];   // [col][k-in-chunk]
    __shared__ float d_sh[128];
    __shared__ float s_sh[64];
    __shared__ float bias_sh[128];

    int tid = threadIdx.x;
    int lane = tid & 31, wid = tid >> 5;
    int warp_m = wid & 3, warp_n = wid >> 2;     // warp tile: 32 rows x 64 cols
    int qr = lane >> 2, qk = lane & 3;
    int tileRow0 = blockIdx.x * 128;
    int batch = blockIdx.x >> 4;                 // 16 tiles per batch

    if (tid < 128) { d_sh[tid] = 0.f; bias_sh[tid] = g_bias[tid]; }
    if (tid < 64) s_sh[tid] = 0.f;

    float acc[2][8][4];
    #pragma unroll
    for (int mt = 0; mt < 2; mt++)
        #pragma unroll
        for (int nt = 0; nt < 8; nt++)
            #pragma unroll
            for (int c = 0; c < 4; c++) acc[mt][nt][c] = 0.f;

    const float* Vbase = Vmat + (size_t)tileRow0 * VD;
    int lrow = tid >> 3;      // base row within the 32-row load slab
    int lkq  = tid & 7;       // float4 index within 32-k chunk

    float4 ra[4], rb[4];
    // prefetch chunk 0
    #pragma unroll
    for (int i = 0; i < 4; i++) {
        int r = i * 32 + lrow;
        ra[i] = *(const float4*)(Vbase + (size_t)r * VD + lkq * 4);
        rb[i] = *(const float4*)(g_W + r * 256 + lkq * 4);
    }

    for (int kc = 0; kc < 8; kc++) {
        __syncthreads();
        #pragma unroll
        for (int i = 0; i < 4; i++) {
            int r = i * 32 + lrow;
            uint4 a, b;
            a.x = to_tf32(ra[i].x); a.y = to_tf32(ra[i].y);
            a.z = to_tf32(ra[i].z); a.w = to_tf32(ra[i].w);
            b.x = to_tf32(rb[i].x); b.y = to_tf32(rb[i].y);
            b.z = to_tf32(rb[i].z); b.w = to_tf32(rb[i].w);
            *(uint4*)&As[r][lkq * 4] = a;
            *(uint4*)&Bs[r][lkq * 4] = b;
        }
        __syncthreads();
        if (kc < 7) {
            int k0 = (kc + 1) * 32;
            #pragma unroll
            for (int i = 0; i < 4; i++) {
                int r = i * 32 + lrow;
                ra[i] = *(const float4*)(Vbase + (size_t)r * VD + k0 + lkq * 4);
                rb[i] = *(const float4*)(g_W + r * 256 + k0 + lkq * 4);
            }
        }
        #pragma unroll
        for (int ks = 0; ks < 4; ks++) {
            int kb = ks * 8 + qk;
            uint32_t af[2][4];
            #pragma unroll
            for (int mt = 0; mt < 2; mt++) {
                int r = warp_m * 32 + mt * 16 + qr;
                af[mt][0] = As[r][kb];
                af[mt][1] = As[r + 8][kb];
                af[mt][2] = As[r][kb + 4];
                af[mt][3] = As[r + 8][kb + 4];
            }
            uint32_t bf[8][2];
            #pragma unroll
            for (int nt = 0; nt < 8; nt++) {
                int c = warp_n * 64 + nt * 8 + qr;
                bf[nt][0] = Bs[c][kb];
                bf[nt][1] = Bs[c][kb + 4];
            }
            #pragma unroll
            for (int mt = 0; mt < 2; mt++)
                #pragma unroll
                for (int nt = 0; nt < 8; nt++)
                    mma_tf32(acc[mt][nt], af[mt], bf[nt]);
        }
    }

    // ---- epilogue: bias+relu, d per row, dr, store right, accumulate s ----
    float be[8], bo[8];
    #pragma unroll
    for (int nt = 0; nt < 8; nt++) {
        int c0 = warp_n * 64 + nt * 8 + qk * 2;
        be[nt] = bias_sh[c0];
        bo[nt] = bias_sh[c0 + 1];
    }

    #pragma unroll
    for (int mt = 0; mt < 2; mt++) {
        #pragma unroll
        for (int h = 0; h < 2; h++) {
            float dpart = 0.f;
            #pragma unroll
            for (int nt = 0; nt < 8; nt++) {
                float rv = fmaxf(acc[mt][nt][h * 2]     + be[nt], 0.f);
                float lv = fmaxf(acc[mt][nt][h * 2 + 1] + bo[nt], 0.f);
                acc[mt][nt][h * 2] = rv;
                acc[mt][nt][h * 2 + 1] = lv;
                dpart = fmaf(rv, lv, dpart);
            }
            dpart += __shfl_xor_sync(0xffffffff, dpart, 1);
            dpart += __shfl_xor_sync(0xffffffff, dpart, 2);
            if (qk == 0) {
                int rl = warp_m * 32 + mt * 16 + h * 8 + qr;
                atomicAdd(&d_sh[rl], dpart);
            }
        }
    }
    __syncthreads();

    float s_t[8];
    #pragma unroll
    for (int nt = 0; nt < 8; nt++) s_t[nt] = 0.f;

    #pragma unroll
    for (int mt = 0; mt < 2; mt++) {
        #pragma unroll
        for (int h = 0; h < 2; h++) {
            int rl = warp_m * 32 + mt * 16 + h * 8 + qr;
            float dr = rsqrtf(d_sh[rl] + EPS_DIAG);
            int row = tileRow0 + rl;
            if (warp_n == 0 && qk == 0) g_dr[row] = dr;
            float* rp = g_right + (size_t)row * LR + warp_n * 32;
            #pragma unroll
            for (int nt = 0; nt < 8; nt++) {
                rp[nt * 4 + qk] = acc[mt][nt][h * 2];
                s_t[nt] = fmaf(dr, acc[mt][nt][h * 2 + 1], s_t[nt]);
            }
        }
    }
    #pragma unroll
    for (int off = 4; off <= 16; off <<= 1)
        #pragma unroll
        for (int nt = 0; nt < 8; nt++)
            s_t[nt] += __shfl_xor_sync(0xffffffff, s_t[nt], off);
    if (qr == 0) {
        #pragma unroll
        for (int nt = 0; nt < 8; nt++)
            atomicAdd(&s_sh[warp_n * 32 + nt * 4 + qk], s_t[nt]);
    }
    __syncthreads();
    if (tid < 64) atomicAdd(&g_s[batch * LR + tid], s_sh[tid]);
}

// ---------------------------------------------------------------------------
// Kernel D: c[m] = N+1 - dr[m]*(s . right[m]); v_final += (1/N)*c[m]*Vmat[m,:]
__global__ void __launch_bounds__(256) k_final(const float* __restrict__ Vmat)
{
    __shared__ float s_sh[64];
    __shared__ float c_sh[256];
    int tid = threadIdx.x;
    int b = blockIdx.y;
    int m0 = blockIdx.x * 256;

    if (tid < 64) s_sh[tid] = g_s[b * LR + tid];
    __syncthreads();

    int row = b * N + m0 + tid;
    const float4* rp = (const float4*)(g_right + (size_t)row * LR);
    float dot = 0.f;
    #pragma unroll
    for (int q = 0; q < 16; q++) {
        float4 v = rp[q];
        dot = fmaf(v.x, s_sh[q * 4 + 0], dot);
        dot = fmaf(v.y, s_sh[q * 4 + 1], dot);
        dot = fmaf(v.z, s_sh[q * 4 + 2], dot);
        dot = fmaf(v.w, s_sh[q * 4 + 3], dot);
    }
    c_sh[tid] = (float)(N + 1) - g_dr[row] * dot;
    __syncthreads();

    const float* Vp = Vmat + ((size_t)b * N + m0) * VD + tid;
    float vacc = 0.f;
    #pragma unroll 8
    for (int m = 0; m < 256; m++) vacc = fmaf(c_sh[m], Vp[(size_t)m * VD], vacc);
    atomicAdd(&g_vfinal[b * VD + tid], vacc * (1.0f / (float)N));
}

// ---------------------------------------------------------------------------
// Kernel E: feat = v_final @ W_lin^T + b_lin; BatchNorm over B (biased var).
// grid 128, block 512: block handles 2 embed cols.
__global__ void __launch_bounds__(512) k_bn(const float* __restrict__ W_lin,
                                            const float* __restrict__ b_lin,
                                            const float* __restrict__ gamma,
                                            const float* __restrict__ beta,
                                            float* __restrict__ out)
{
    int tid = threadIdx.x;
    int w = tid >> 5, lane = tid & 31;
    int e_loc = w >> 3;                      // 0..1
    int e = blockIdx.x * 2 + e_loc;
    int bat = (w & 7) * 4 + (lane >> 3);     // 0..31
    int dl = lane & 7;

    const float* wrow = W_lin + e * VD;
    const float* vrow = g_vfinal + bat * VD;
    float part = 0.f;
    #pragma unroll
    for (int j = 0; j < 32; j++) {
        int d = dl + 8 * j;
        part = fmaf(vrow[d], wrow[d], part);
    }
    part += __shfl_xor_sync(0xffffffff, part, 1);
    part += __shfl_xor_sync(0xffffffff, part, 2);
    part += __shfl_xor_sync(0xffffffff, part, 4);

    __shared__ float feats[2][32];
    if (dl == 0) feats[e_loc][bat] = part + b_lin[e];
    __syncthreads();

    if (tid < 64) {
        int el = tid >> 5;
        int bb = tid & 31;
        float f = feats[el][bb];
        float mu = f;
        #pragma unroll
        for (int off = 16; off >= 1; off >>= 1) mu += __shfl_xor_sync(0xffffffff, mu, off);
        mu *= (1.0f / 32.0f);
        float df = f - mu;
        float vv = df * df;
        #pragma unroll
        for (int off = 16; off >= 1; off >>= 1) vv += __shfl_xor_sync(0xffffffff, vv, off);
        vv *= (1.0f / 32.0f);
        int eo = blockIdx.x * 2 + el;
        out[bb * EMB + eo] = df * rsqrtf(vv + EPS_BN) * gamma[eo] + beta[eo];
    }
}

// ---------------------------------------------------------------------------
extern "C" void kernel_launch(void* const* d_in, const int* in_sizes, int n_in,
                              void* d_out, int out_size)
{
    const float* Vmat  = (const float*)d_in[0];
    const float* U1_v  = (const float*)d_in[1];
    const float* U1_g  = (const float*)d_in[2];
    const float* U1_b  = (const float*)d_in[3];
    const float* U2_v  = (const float*)d_in[4];
    const float* U2_g  = (const float*)d_in[5];
    const float* U2_b  = (const float*)d_in[6];
    const float* W_lin = (const float*)d_in[7];
    const float* b_lin = (const float*)d_in[8];
    const float* gamma = (const float*)d_in[9];
    const float* beta  = (const float*)d_in[10];
    float* out = (float*)d_out;

    k_weightnorm<<<128, 256>>>(U1_v, U1_g, U1_b, U2_v, U2_g, U2_b);
    k_main<<<ROWS / 128, 256>>>(Vmat);
    k_final<<<dim3(8, B), 256>>>(Vmat);
    k_bn<<<EMB / 2, 512>>>(W_lin, b_lin, gamma, beta, out);
}